// round 16
// baseline (speedup 1.0000x reference)
#include <cuda_runtime.h>
#include <cuda_bf16.h>
#include <cuda_fp16.h>
#include <math.h>
#include <stdint.h>

#define NB   16
#define TQ   2048
#define TV   2048
#define DEC  1024
#define ENC  512

// ---------------- scratch (device globals; no allocation allowed) ----------
// NOTE: bias provably cancels (scores only enter through softmax; Q·b is a
// per-row constant), so no bias is applied anywhere.
__device__ __nv_bfloat16 g_q2  [(size_t)NB * TQ * (2 * DEC)];   // query  split [hi|lo]
__device__ __nv_bfloat16 g_v2  [(size_t)NB * TV * (2 * ENC)];   // value  split [hi|lo]
__device__ __nv_bfloat16 g_w2  [(size_t)ENC * (2 * DEC)];       // W      split [hi|lo] (K-major in d)
__device__ __nv_bfloat16 g_qw2 [(size_t)NB * TQ * (2 * ENC)];   // Q·W^T  split (GEMM1' epilogue)
__device__ __half        g_vt16[(size_t)NB * ENC * TV];         // value^T fp16
__device__ __half        g_p16 [(size_t)NB * TQ * TV];          // probs fp16 (softmax)
__device__ float         g_scores[(size_t)NB * TQ * TV];        // fp32 scores

// ========================= PTX helpers =====================================
static __device__ __forceinline__ uint32_t smem_u32(const void* p) {
    uint32_t a;
    asm("{ .reg .u64 t; cvta.to.shared.u64 t, %1; cvt.u32.u64 %0, t; }"
        : "=r"(a) : "l"(p));
    return a;
}

#define CP_ASYNC16(dst, src) \
    asm volatile("cp.async.cg.shared.global [%0], [%1], 16;" :: "r"(dst), "l"(src) : "memory")
#define CP_COMMIT() asm volatile("cp.async.commit_group;" ::: "memory")
#define CP_WAIT1()  asm volatile("cp.async.wait_group 1;" ::: "memory")
#define CP_WAIT0()  asm volatile("cp.async.wait_group 0;" ::: "memory")

#define LDMX4(r0, r1, r2, r3, addr) \
    asm volatile("ldmatrix.sync.aligned.m8n8.x4.shared.b16 {%0,%1,%2,%3}, [%4];" \
        : "=r"(r0), "=r"(r1), "=r"(r2), "=r"(r3) : "r"(addr))

#define MMA_BF16(d, a, b) \
    asm volatile("mma.sync.aligned.m16n8k16.row.col.f32.bf16.bf16.f32 " \
        "{%0,%1,%2,%3}, {%4,%5,%6,%7}, {%8,%9}, {%0,%1,%2,%3};" \
        : "+f"((d)[0]), "+f"((d)[1]), "+f"((d)[2]), "+f"((d)[3]) \
        : "r"((a)[0]), "r"((a)[1]), "r"((a)[2]), "r"((a)[3]), \
          "r"((b)[0]), "r"((b)[1]))

#define MMA_F16(d, a, b) \
    asm volatile("mma.sync.aligned.m16n8k16.row.col.f32.f16.f16.f32 " \
        "{%0,%1,%2,%3}, {%4,%5,%6,%7}, {%8,%9}, {%0,%1,%2,%3};" \
        : "+f"((d)[0]), "+f"((d)[1]), "+f"((d)[2]), "+f"((d)[3]) \
        : "r"((a)[0]), "r"((a)[1]), "r"((a)[2]), "r"((a)[3]), \
          "r"((b)[0]), "r"((b)[1]))

#define SMEM_SWZ(off) ((off) ^ (((off) >> 3) & 0x70))

static __device__ __forceinline__ void split2(float v, __nv_bfloat16& h, __nv_bfloat16& l) {
    h = __float2bfloat16(v);
    l = __float2bfloat16(v - __bfloat162float(h));
}

// ========================= mma.sync GEMM ===================================
// CTA tile 128x128, 128 threads, 4 warps in 2x2 grid, warp tile 64x64.
// (8 LDSM.x4 per 32 MMAs per ks-step — half the LDSM/MMA of the 32x64 layout;
//  2 CTAs/SM preserved; 256-reg/thread budget removes the spill risk.)
// MODE 0: logical A[M,3K]*B[N,3K]^T with A blocks [hi,hi,lo], B [hi,lo,hi],
//         operands stored dedup'd bf16 [hi|lo] (row = 2K elems). nIter=3*K/64.
// MODE 1: plain fp16 A[M,K]*B[N,K]^T (row = K elems). nIter=K/64.
// EPI=0: fp32 store to C (ldc elems row stride, sC elems batch stride).
// EPI=1: split bf16 [hi|lo] store to O3 (lo at +ldc/2, batch stride sC elems).
// sAb/sBb are BYTE strides per batch.
#define TILE_BYTES 16384u
#define STAGE_BYTES (2u * TILE_BYTES)
#define GEMM_DSMEM (2 * 32768 + 1024)

template<int EPI, int MODE>
__global__ __launch_bounds__(128, 2)
void gemm_mma(const void* __restrict__ A, const void* __restrict__ B,
              float* __restrict__ C, __nv_bfloat16* __restrict__ O3,
              int K, long long sAb, long long sBb, long long sC, int ldc)
{
    extern __shared__ char dsm[];
    const int tid  = threadIdx.x;
    const int wid  = tid >> 5;
    const int lane = tid & 31;
    const int bz   = blockIdx.z;
    const int rowBase = blockIdx.y * 128;
    const int colBase = blockIdx.x * 128;
    const int n1    = K >> 6;
    const int nIter = (MODE == 0) ? 3 * n1 : n1;

    const int warp_m = wid & 1;          // 0..1  -> 64-row slab
    const int warp_n = wid >> 1;         // 0..1  -> 64-col slab

    const uint32_t tile0 = (smem_u32(dsm) + 1023u) & ~1023u;   // [A0][B0][A1][B1]

    const char* gA = (const char*)A + bz * sAb;
    const char* gB = (const char*)B + bz * sBb;
    const int cr = tid >> 3;             // 0..15
    const int ch = (tid & 7) * 16;       // 16B chunk in 128B row
    const long long ldab = (MODE == 0) ? (long long)K * 4 : (long long)K * 2;  // bytes/row

    auto fill = [&](int buf, int i) {
        const uint32_t tA = tile0 + (uint32_t)buf * STAGE_BYTES;
        const uint32_t tB = tA + TILE_BYTES;
        int ba, bb;
        if (MODE == 0) {
            const int s = (i >= 2 * n1) ? 2 : (i >= n1 ? 1 : 0);
            const int j = i - s * n1;
            ba = (s == 2) ? (n1 + j) : j;            // A: [hi,hi,lo]
            bb = (s == 1) ? (n1 + j) : j;            // B: [hi,lo,hi]
        } else {
            ba = i; bb = i;
        }
        const long long kbA = (long long)ba * 128;   // 64 elems = 128 bytes
        const long long kbB = (long long)bb * 128;
#pragma unroll
        for (int r = 0; r < 8; r++) {
            const int rit = r * 16 + cr;             // 0..127
            const uint32_t so = SMEM_SWZ((uint32_t)(rit * 128 + ch));
            CP_ASYNC16(tA + so, gA + (long long)(rowBase + rit) * ldab + kbA + ch);
            CP_ASYNC16(tB + so, gB + (long long)(colBase + rit) * ldab + kbB + ch);
        }
        CP_COMMIT();
    };

    float acc[4][8][4];
#pragma unroll
    for (int mt = 0; mt < 4; mt++)
#pragma unroll
        for (int nt = 0; nt < 8; nt++)
#pragma unroll
            for (int c = 0; c < 4; c++) acc[mt][nt][c] = 0.f;

    // per-lane ldmatrix addressing
    const int lrow = lane & 7;
    const int lg   = lane >> 3;          // 0..3 address group

    fill(0, 0);
    for (int i = 0; i < nIter; i++) {
        const int buf = i & 1;
        if (i + 1 < nIter) { fill(buf ^ 1, i + 1); CP_WAIT1(); }
        else               { CP_WAIT0(); }
        __syncthreads();

        const uint32_t tA = tile0 + (uint32_t)buf * STAGE_BYTES;
        const uint32_t tB = tA + TILE_BYTES;

#pragma unroll
        for (int ks = 0; ks < 4; ks++) {
            const int kb = ks * 16;
            uint32_t af[4][4];
#pragma unroll
            for (int mt = 0; mt < 4; mt++) {
                // groups: g0: m0-7,k0 | g1: m8-15,k0 | g2: m0-7,k8 | g3: m8-15,k8
                const int row = warp_m * 64 + mt * 16 + (lg & 1) * 8 + lrow;
                const int kk  = kb + (lg >> 1) * 8;
                LDMX4(af[mt][0], af[mt][1], af[mt][2], af[mt][3],
                      tA + SMEM_SWZ((uint32_t)(row * 128 + kk * 2)));
            }
            uint32_t bf[8][2];
#pragma unroll
            for (int nt2 = 0; nt2 < 4; nt2++) {
                // groups: g0: n0-7,k0 | g1: n0-7,k8 | g2: n8-15,k0 | g3: n8-15,k8
                const int nn = warp_n * 64 + nt2 * 16 + (lg >> 1) * 8 + lrow;
                const int kk = kb + (lg & 1) * 8;
                uint32_t r0, r1, r2, r3;
                LDMX4(r0, r1, r2, r3, tB + SMEM_SWZ((uint32_t)(nn * 128 + kk * 2)));
                bf[2 * nt2][0] = r0;     bf[2 * nt2][1] = r1;
                bf[2 * nt2 + 1][0] = r2; bf[2 * nt2 + 1][1] = r3;
            }
#pragma unroll
            for (int mt = 0; mt < 4; mt++)
#pragma unroll
                for (int nt = 0; nt < 8; nt++) {
                    if (MODE == 0) { MMA_BF16(acc[mt][nt], af[mt], bf[nt]); }
                    else           { MMA_F16 (acc[mt][nt], af[mt], bf[nt]); }
                }
        }
        __syncthreads();
    }

    // -------- epilogue (acc in registers) ----------------------------------
    const int erow = (lane >> 2);        // 0..7
    const int ecol = (lane & 3) * 2;

    if (EPI == 0) {
        float* cb = C + bz * sC;
#pragma unroll
        for (int mt = 0; mt < 4; mt++) {
#pragma unroll
            for (int nt = 0; nt < 8; nt++) {
                const long long r0 = rowBase + warp_m * 64 + mt * 16 + erow;
                const int cc = colBase + warp_n * 64 + nt * 8 + ecol;
                float2 lo = make_float2(acc[mt][nt][0], acc[mt][nt][1]);
                float2 hi = make_float2(acc[mt][nt][2], acc[mt][nt][3]);
                *(float2*)(cb + r0 * ldc + cc)       = lo;
                *(float2*)(cb + (r0 + 8) * ldc + cc) = hi;
            }
        }
    } else {
        // split bf16 [hi | lo] store: hi at col cc, lo at cc + ldc/2
        __nv_bfloat16* ob = O3 + bz * sC;
        const int halfOff = ldc >> 1;
#pragma unroll
        for (int mt = 0; mt < 4; mt++) {
#pragma unroll
            for (int nt = 0; nt < 8; nt++) {
                const int cc = colBase + warp_n * 64 + nt * 8 + ecol;
#pragma unroll
                for (int half = 0; half < 2; half++) {
                    const long long r0 = rowBase + warp_m * 64 + mt * 16 + erow + 8 * half;
                    const float f0 = acc[mt][nt][2 * half + 0];
                    const float f1 = acc[mt][nt][2 * half + 1];
                    __nv_bfloat16 h0, l0, h1, l1;
                    split2(f0, h0, l0);
                    split2(f1, h1, l1);
                    __nv_bfloat16* o = ob + r0 * (long long)ldc + cc;
                    *(__nv_bfloat162*)(o)           = __halves2bfloat162(h0, h1);
                    *(__nv_bfloat162*)(o + halfOff) = __halves2bfloat162(l0, l1);
                }
            }
        }
    }
}

// ========================= conversion kernels ==============================
// fp32 [rows,K] -> bf16 [rows,2K]  layout [hi | lo]
// If octx != nullptr (query path): also copy fp32 into out_ctx cols [512:1536).
__global__ __launch_bounds__(256)
void conv_P(const float* __restrict__ in, __nv_bfloat16* __restrict__ out, int K,
            float* __restrict__ octx)
{
    const long long idx = (long long)blockIdx.x * 256 + threadIdx.x;   // float4 id
    const int K4 = K >> 2;
    const long long row = idx / K4;
    const int c = (int)(idx - row * K4) * 4;
    float4 v = ((const float4*)in)[idx];
    __nv_bfloat16 h[4], l[4];
    split2(v.x, h[0], l[0]); split2(v.y, h[1], l[1]);
    split2(v.z, h[2], l[2]); split2(v.w, h[3], l[3]);
    __nv_bfloat16* ob = out + row * (2LL * K) + c;
    ((__nv_bfloat162*)ob)[0]       = __halves2bfloat162(h[0], h[1]);
    ((__nv_bfloat162*)ob)[1]       = __halves2bfloat162(h[2], h[3]);
    ((__nv_bfloat162*)(ob + K))[0] = __halves2bfloat162(l[0], l[1]);
    ((__nv_bfloat162*)(ob + K))[1] = __halves2bfloat162(l[2], l[3]);
    if (octx) {
        ((float4*)octx)[row * 384 + 128 + (c >> 2)] = v;
    }
}

// value: fp32 [b][TV,ENC] -> v2 split bf16 [b][TV,2*ENC]  AND  vt16 fp16 [b][ENC,TV]
__global__ void conv_V(const float* __restrict__ in, __nv_bfloat16* __restrict__ v2,
                       __half* __restrict__ vt16)
{
    __shared__ float t[32][33];
    const long long bi = blockIdx.z;
    const float* src = in + bi * (long long)TV * ENC;
    __nv_bfloat16* d2 = v2 + bi * (long long)TV * (2 * ENC);
    __half* dt = vt16 + bi * (long long)ENC * TV;
    const int c0 = blockIdx.x * 32;      // ENC dim
    const int r0 = blockIdx.y * 32;      // TV dim
    const int tx = threadIdx.x;
    for (int i = threadIdx.y; i < 32; i += 8) {
        const float val = src[(long long)(r0 + i) * ENC + c0 + tx];
        t[i][tx] = val;
        __nv_bfloat16 h, l;
        split2(val, h, l);
        __nv_bfloat16* o = d2 + (long long)(r0 + i) * (2 * ENC) + c0 + tx;
        o[0] = h; o[ENC] = l;
    }
    __syncthreads();
    for (int i = threadIdx.y; i < 32; i += 8)
        dt[(long long)(c0 + i) * TV + r0 + tx] = __float2half_rn(t[tx][i]);
}

// softmax rows -> fp16 probs
__global__ __launch_bounds__(256)
void softmax_split(const float* __restrict__ S, __half* __restrict__ P16)
{
    const long long row = blockIdx.x;
    const float* p = S + row * (long long)TV;
    __half* o = P16 + row * (long long)TV;
    const int tid = threadIdx.x;

    float vals[8];
    float lmax = -3.0e38f;
#pragma unroll
    for (int i = 0; i < 2; i++) {
        float4 t = ((const float4*)p)[tid + i * 256];
        vals[i * 4 + 0] = t.x; vals[i * 4 + 1] = t.y;
        vals[i * 4 + 2] = t.z; vals[i * 4 + 3] = t.w;
        lmax = fmaxf(lmax, fmaxf(fmaxf(t.x, t.y), fmaxf(t.z, t.w)));
    }

    __shared__ float red[256];
    red[tid] = lmax;
    __syncthreads();
    for (int s = 128; s > 0; s >>= 1) {
        if (tid < s) red[tid] = fmaxf(red[tid], red[tid + s]);
        __syncthreads();
    }
    const float m = red[0];
    __syncthreads();

    float lsum = 0.f;
#pragma unroll
    for (int i = 0; i < 8; i++) { vals[i] = expf(vals[i] - m); lsum += vals[i]; }
    red[tid] = lsum;
    __syncthreads();
    for (int s = 128; s > 0; s >>= 1) {
        if (tid < s) red[tid] += red[tid + s];
        __syncthreads();
    }
    const float inv = 1.f / red[0];

#pragma unroll
    for (int i = 0; i < 2; i++) {
        const int e0 = 4 * tid + 1024 * i;
        __half2 a = __floats2half2_rn(vals[i * 4 + 0] * inv, vals[i * 4 + 1] * inv);
        __half2 b = __floats2half2_rn(vals[i * 4 + 2] * inv, vals[i * 4 + 3] * inv);
        ((__half2*)(o + e0))[0] = a;
        ((__half2*)(o + e0))[1] = b;
    }
}

// alignment_t: transpose fp16 probs -> fp32 [b][v][q]
__global__ void transpose_out(const __half* __restrict__ P16, float* __restrict__ out)
{
    __shared__ float t[32][33];
    const int b = blockIdx.z;
    const __half* base = P16 + (long long)b * TQ * TV;
    float* dst = out + (long long)b * TV * TQ;
    const int v0 = blockIdx.x * 32, q0 = blockIdx.y * 32;
    const int tx = threadIdx.x;
    for (int i = threadIdx.y; i < 32; i += 8)
        t[i][tx] = __half2float(base[(long long)(q0 + i) * TV + v0 + tx]);
    __syncthreads();
    for (int i = threadIdx.y; i < 32; i += 8)
        dst[(long long)(v0 + i) * TQ + q0 + tx] = t[tx][i];
}

// ========================= launch ==========================================
extern "C" void kernel_launch(void* const* d_in, const int* in_sizes, int n_in,
                              void* d_out, int out_size)
{
    (void)in_sizes; (void)n_in; (void)out_size;
    const float* q = (const float*)d_in[0];   // [16,2048,1024]
    const float* v = (const float*)d_in[1];   // [16,2048,512]
    const float* W = (const float*)d_in[2];   // [512,1024]
    // d_in[3] = bias: provably cancels through softmax (per-row constant Q·b).

    float* out       = (float*)d_out;
    float* out_ctx   = out;                                      // [16,2048,1536]
    float* out_align = out + (long long)NB * TQ * 1536;          // [16,2048,2048]

    __nv_bfloat16 *q2, *v2, *w2, *qw2;
    __half *vt16, *p16;
    float* scores;
    cudaGetSymbolAddress((void**)&q2,     g_q2);
    cudaGetSymbolAddress((void**)&v2,     g_v2);
    cudaGetSymbolAddress((void**)&w2,     g_w2);
    cudaGetSymbolAddress((void**)&qw2,    g_qw2);
    cudaGetSymbolAddress((void**)&vt16,   g_vt16);
    cudaGetSymbolAddress((void**)&p16,    g_p16);
    cudaGetSymbolAddress((void**)&scores, g_scores);

    cudaFuncSetAttribute(gemm_mma<0,0>, cudaFuncAttributeMaxDynamicSharedMemorySize, GEMM_DSMEM);
    cudaFuncSetAttribute(gemm_mma<1,0>, cudaFuncAttributeMaxDynamicSharedMemorySize, GEMM_DSMEM);
    cudaFuncSetAttribute(gemm_mma<0,1>, cudaFuncAttributeMaxDynamicSharedMemorySize, GEMM_DSMEM);

    // operand prep (conv_P on query also performs the out_ctx query copy)
    conv_P<<<(NB * TQ * (DEC / 4)) / 256, 256>>>(q, q2, DEC, out_ctx);
    conv_P<<<(ENC * (DEC / 4)) / 256, 256>>>(W, w2, DEC, nullptr);   // W split, K-major in d
    conv_V<<<dim3(ENC / 32, TV / 32, NB), dim3(32, 8)>>>(v, v2, vt16);

    // G1': qw2 = split(Q @ W^T)   [M=TQ, N=ENC, K=1024], bf16 3-pass
    gemm_mma<1,0><<<dim3(ENC / 128, TQ / 128, NB), 128, GEMM_DSMEM>>>(
        q2, w2, nullptr, qw2,
        DEC, (long long)TQ * (2 * DEC) * 2, 0LL,
        (long long)TQ * (2 * ENC), 2 * ENC);

    // G2': scores = QW @ V^T      [M=TQ, N=TV, K=512], bf16 3-pass
    gemm_mma<0,0><<<dim3(TV / 128, TQ / 128, NB), 128, GEMM_DSMEM>>>(
        qw2, v2, scores, nullptr,
        ENC, (long long)TQ * (2 * ENC) * 2, (long long)TV * (2 * ENC) * 2,
        (long long)TQ * TV, TV);

    // softmax -> p16
    softmax_split<<<NB * TQ, 256>>>(scores, p16);

    // G3: context = probs @ value [M=TQ, N=ENC, K=2048], fp16 1-pass
    gemm_mma<0,1><<<dim3(ENC / 128, TQ / 128, NB), 128, GEMM_DSMEM>>>(
        p16, vt16, out_ctx, nullptr,
        TV, (long long)TQ * TV * 2, (long long)ENC * TV * 2,
        (long long)TQ * 1536, 1536);

    // alignment_t = transpose(p16)
    transpose_out<<<dim3(TV / 32, TQ / 32, NB), dim3(32, 8)>>>(p16, out_align);
}

// round 17
// speedup vs baseline: 1.4807x; 1.4807x over previous
#include <cuda_runtime.h>
#include <cuda_bf16.h>
#include <cuda_fp16.h>
#include <math.h>
#include <stdint.h>

#define NB   16
#define TQ   2048
#define TV   2048
#define DEC  1024
#define ENC  512

// ---------------- scratch (device globals; no allocation allowed) ----------
// NOTE: bias provably cancels (scores only enter through softmax; Q·b is a
// per-row constant), so no bias is applied anywhere.
__device__ __nv_bfloat16 g_q2  [(size_t)NB * TQ * (2 * DEC)];   // query  split [hi|lo]
__device__ __nv_bfloat16 g_v2  [(size_t)NB * TV * (2 * ENC)];   // value  split [hi|lo]
__device__ __nv_bfloat16 g_w2  [(size_t)ENC * (2 * DEC)];       // W      split [hi|lo] (K-major in d)
__device__ __nv_bfloat16 g_qw2 [(size_t)NB * TQ * (2 * ENC)];   // Q·W^T  split (GEMM1' epilogue)
__device__ __half        g_vt16[(size_t)NB * ENC * TV];         // value^T fp16
__device__ __half        g_p16 [(size_t)NB * TQ * TV];          // probs fp16 (softmax)
__device__ float         g_scores[(size_t)NB * TQ * TV];        // fp32 scores

// ========================= PTX helpers =====================================
static __device__ __forceinline__ uint32_t smem_u32(const void* p) {
    uint32_t a;
    asm("{ .reg .u64 t; cvta.to.shared.u64 t, %1; cvt.u32.u64 %0, t; }"
        : "=r"(a) : "l"(p));
    return a;
}

#define CP_ASYNC16(dst, src) \
    asm volatile("cp.async.cg.shared.global [%0], [%1], 16;" :: "r"(dst), "l"(src) : "memory")
#define CP_COMMIT() asm volatile("cp.async.commit_group;" ::: "memory")
#define CP_WAIT1()  asm volatile("cp.async.wait_group 1;" ::: "memory")
#define CP_WAIT0()  asm volatile("cp.async.wait_group 0;" ::: "memory")

#define LDMX4(r0, r1, r2, r3, addr) \
    asm volatile("ldmatrix.sync.aligned.m8n8.x4.shared.b16 {%0,%1,%2,%3}, [%4];" \
        : "=r"(r0), "=r"(r1), "=r"(r2), "=r"(r3) : "r"(addr))

#define MMA_BF16(d, a, b) \
    asm volatile("mma.sync.aligned.m16n8k16.row.col.f32.bf16.bf16.f32 " \
        "{%0,%1,%2,%3}, {%4,%5,%6,%7}, {%8,%9}, {%0,%1,%2,%3};" \
        : "+f"((d)[0]), "+f"((d)[1]), "+f"((d)[2]), "+f"((d)[3]) \
        : "r"((a)[0]), "r"((a)[1]), "r"((a)[2]), "r"((a)[3]), \
          "r"((b)[0]), "r"((b)[1]))

#define MMA_F16(d, a, b) \
    asm volatile("mma.sync.aligned.m16n8k16.row.col.f32.f16.f16.f32 " \
        "{%0,%1,%2,%3}, {%4,%5,%6,%7}, {%8,%9}, {%0,%1,%2,%3};" \
        : "+f"((d)[0]), "+f"((d)[1]), "+f"((d)[2]), "+f"((d)[3]) \
        : "r"((a)[0]), "r"((a)[1]), "r"((a)[2]), "r"((a)[3]), \
          "r"((b)[0]), "r"((b)[1]))

#define SMEM_SWZ(off) ((off) ^ (((off) >> 3) & 0x70))

static __device__ __forceinline__ void split2(float v, __nv_bfloat16& h, __nv_bfloat16& l) {
    h = __float2bfloat16(v);
    l = __float2bfloat16(v - __bfloat162float(h));
}

// ========================= mma.sync GEMM (R12 winner, verbatim) ============
// CTA 128x128, 256 threads, 8 warps (4x2), warp tile 32x64, 2 CTAs/SM.
// MODE 0: logical A[M,3K]*B[N,3K]^T with A blocks [hi,hi,lo], B [hi,lo,hi],
//         operands stored dedup'd bf16 [hi|lo] (row = 2K elems). nIter=3*K/64.
// MODE 1: plain fp16 A[M,K]*B[N,K]^T (row = K elems). nIter=K/64.
// EPI=0: fp32 store to C (ldc elems row stride, sC elems batch stride).
// EPI=1: split bf16 [hi|lo] store to O3 (lo at +ldc/2, batch stride sC elems).
// sAb/sBb are BYTE strides per batch.
#define TILE_BYTES 16384u
#define STAGE_BYTES (2u * TILE_BYTES)
#define GEMM_DSMEM (2 * 32768 + 1024)

template<int EPI, int MODE>
__global__ __launch_bounds__(256, 2)
void gemm_mma(const void* __restrict__ A, const void* __restrict__ B,
              float* __restrict__ C, __nv_bfloat16* __restrict__ O3,
              int K, long long sAb, long long sBb, long long sC, int ldc)
{
    extern __shared__ char dsm[];
    const int tid  = threadIdx.x;
    const int wid  = tid >> 5;
    const int lane = tid & 31;
    const int bz   = blockIdx.z;
    const int rowBase = blockIdx.y * 128;
    const int colBase = blockIdx.x * 128;
    const int n1    = K >> 6;
    const int nIter = (MODE == 0) ? 3 * n1 : n1;

    const int warp_m = wid & 3;          // 0..3  -> 32-row slab
    const int warp_n = wid >> 2;         // 0..1  -> 64-col slab

    const uint32_t tile0 = (smem_u32(dsm) + 1023u) & ~1023u;   // [A0][B0][A1][B1]

    const char* gA = (const char*)A + bz * sAb;
    const char* gB = (const char*)B + bz * sBb;
    const int cr = tid >> 3;             // 0..31
    const int ch = (tid & 7) * 16;       // 16B chunk in 128B row
    const long long ldab = (MODE == 0) ? (long long)K * 4 : (long long)K * 2;  // bytes/row

    auto fill = [&](int buf, int i) {
        const uint32_t tA = tile0 + (uint32_t)buf * STAGE_BYTES;
        const uint32_t tB = tA + TILE_BYTES;
        int ba, bb;
        if (MODE == 0) {
            const int s = (i >= 2 * n1) ? 2 : (i >= n1 ? 1 : 0);
            const int j = i - s * n1;
            ba = (s == 2) ? (n1 + j) : j;            // A: [hi,hi,lo]
            bb = (s == 1) ? (n1 + j) : j;            // B: [hi,lo,hi]
        } else {
            ba = i; bb = i;
        }
        const long long kbA = (long long)ba * 128;   // 64 elems = 128 bytes
        const long long kbB = (long long)bb * 128;
#pragma unroll
        for (int r = 0; r < 4; r++) {
            const int rit = r * 32 + cr;
            const uint32_t so = SMEM_SWZ((uint32_t)(rit * 128 + ch));
            CP_ASYNC16(tA + so, gA + (long long)(rowBase + rit) * ldab + kbA + ch);
            CP_ASYNC16(tB + so, gB + (long long)(colBase + rit) * ldab + kbB + ch);
        }
        CP_COMMIT();
    };

    float acc[2][8][4];
#pragma unroll
    for (int mt = 0; mt < 2; mt++)
#pragma unroll
        for (int nt = 0; nt < 8; nt++)
#pragma unroll
            for (int c = 0; c < 4; c++) acc[mt][nt][c] = 0.f;

    // per-lane ldmatrix addressing
    const int lrow = lane & 7;
    const int lg   = lane >> 3;          // 0..3 address group

    fill(0, 0);
    for (int i = 0; i < nIter; i++) {
        const int buf = i & 1;
        if (i + 1 < nIter) { fill(buf ^ 1, i + 1); CP_WAIT1(); }
        else               { CP_WAIT0(); }
        __syncthreads();

        const uint32_t tA = tile0 + (uint32_t)buf * STAGE_BYTES;
        const uint32_t tB = tA + TILE_BYTES;

#pragma unroll
        for (int ks = 0; ks < 4; ks++) {
            const int kb = ks * 16;
            uint32_t af[2][4];
#pragma unroll
            for (int mt = 0; mt < 2; mt++) {
                const int row = warp_m * 32 + mt * 16 + (lg & 1) * 8 + lrow;
                const int kk  = kb + (lg >> 1) * 8;
                LDMX4(af[mt][0], af[mt][1], af[mt][2], af[mt][3],
                      tA + SMEM_SWZ((uint32_t)(row * 128 + kk * 2)));
            }
            uint32_t bf[8][2];
#pragma unroll
            for (int nt2 = 0; nt2 < 4; nt2++) {
                const int nn = warp_n * 64 + nt2 * 16 + (lg >> 1) * 8 + lrow;
                const int kk = kb + (lg & 1) * 8;
                uint32_t r0, r1, r2, r3;
                LDMX4(r0, r1, r2, r3, tB + SMEM_SWZ((uint32_t)(nn * 128 + kk * 2)));
                bf[2 * nt2][0] = r0;     bf[2 * nt2][1] = r1;
                bf[2 * nt2 + 1][0] = r2; bf[2 * nt2 + 1][1] = r3;
            }
#pragma unroll
            for (int mt = 0; mt < 2; mt++)
#pragma unroll
                for (int nt = 0; nt < 8; nt++) {
                    if (MODE == 0) { MMA_BF16(acc[mt][nt], af[mt], bf[nt]); }
                    else           { MMA_F16 (acc[mt][nt], af[mt], bf[nt]); }
                }
        }
        __syncthreads();
    }

    // -------- epilogue (acc in registers) ----------------------------------
    const int erow = (lane >> 2);        // 0..7
    const int ecol = (lane & 3) * 2;

    if (EPI == 0) {
        float* cb = C + bz * sC;
#pragma unroll
        for (int mt = 0; mt < 2; mt++) {
#pragma unroll
            for (int nt = 0; nt < 8; nt++) {
                const long long r0 = rowBase + warp_m * 32 + mt * 16 + erow;
                const int cc = colBase + warp_n * 64 + nt * 8 + ecol;
                float2 lo = make_float2(acc[mt][nt][0], acc[mt][nt][1]);
                float2 hi = make_float2(acc[mt][nt][2], acc[mt][nt][3]);
                *(float2*)(cb + r0 * ldc + cc)       = lo;
                *(float2*)(cb + (r0 + 8) * ldc + cc) = hi;
            }
        }
    } else {
        // split bf16 [hi | lo] store: hi at col cc, lo at cc + ldc/2
        __nv_bfloat16* ob = O3 + bz * sC;
        const int halfOff = ldc >> 1;
#pragma unroll
        for (int mt = 0; mt < 2; mt++) {
#pragma unroll
            for (int nt = 0; nt < 8; nt++) {
                const int cc = colBase + warp_n * 64 + nt * 8 + ecol;
#pragma unroll
                for (int half = 0; half < 2; half++) {
                    const long long r0 = rowBase + warp_m * 32 + mt * 16 + erow + 8 * half;
                    const float f0 = acc[mt][nt][2 * half + 0];
                    const float f1 = acc[mt][nt][2 * half + 1];
                    __nv_bfloat16 h0, l0, h1, l1;
                    split2(f0, h0, l0);
                    split2(f1, h1, l1);
                    __nv_bfloat16* o = ob + r0 * (long long)ldc + cc;
                    *(__nv_bfloat162*)(o)           = __halves2bfloat162(h0, h1);
                    *(__nv_bfloat162*)(o + halfOff) = __halves2bfloat162(l0, l1);
                }
            }
        }
    }
}

// ========================= conversion kernels ==============================
// fp32 [rows,K] -> bf16 [rows,2K]  layout [hi | lo]
// If octx != nullptr (query path): also copy fp32 into out_ctx cols [512:1536).
__global__ __launch_bounds__(256)
void conv_P(const float* __restrict__ in, __nv_bfloat16* __restrict__ out, int K,
            float* __restrict__ octx)
{
    const long long idx = (long long)blockIdx.x * 256 + threadIdx.x;   // float4 id
    const int K4 = K >> 2;
    const long long row = idx / K4;
    const int c = (int)(idx - row * K4) * 4;
    float4 v = ((const float4*)in)[idx];
    __nv_bfloat16 h[4], l[4];
    split2(v.x, h[0], l[0]); split2(v.y, h[1], l[1]);
    split2(v.z, h[2], l[2]); split2(v.w, h[3], l[3]);
    __nv_bfloat16* ob = out + row * (2LL * K) + c;
    ((__nv_bfloat162*)ob)[0]       = __halves2bfloat162(h[0], h[1]);
    ((__nv_bfloat162*)ob)[1]       = __halves2bfloat162(h[2], h[3]);
    ((__nv_bfloat162*)(ob + K))[0] = __halves2bfloat162(l[0], l[1]);
    ((__nv_bfloat162*)(ob + K))[1] = __halves2bfloat162(l[2], l[3]);
    if (octx) {
        ((float4*)octx)[row * 384 + 128 + (c >> 2)] = v;
    }
}

// value: fp32 [b][TV,ENC] -> v2 split bf16 [b][TV,2*ENC]  AND  vt16 fp16 [b][ENC,TV]
__global__ void conv_V(const float* __restrict__ in, __nv_bfloat16* __restrict__ v2,
                       __half* __restrict__ vt16)
{
    __shared__ float t[32][33];
    const long long bi = blockIdx.z;
    const float* src = in + bi * (long long)TV * ENC;
    __nv_bfloat16* d2 = v2 + bi * (long long)TV * (2 * ENC);
    __half* dt = vt16 + bi * (long long)ENC * TV;
    const int c0 = blockIdx.x * 32;      // ENC dim
    const int r0 = blockIdx.y * 32;      // TV dim
    const int tx = threadIdx.x;
    for (int i = threadIdx.y; i < 32; i += 8) {
        const float val = src[(long long)(r0 + i) * ENC + c0 + tx];
        t[i][tx] = val;
        __nv_bfloat16 h, l;
        split2(val, h, l);
        __nv_bfloat16* o = d2 + (long long)(r0 + i) * (2 * ENC) + c0 + tx;
        o[0] = h; o[ENC] = l;
    }
    __syncthreads();
    for (int i = threadIdx.y; i < 32; i += 8)
        dt[(long long)(c0 + i) * TV + r0 + tx] = __float2half_rn(t[tx][i]);
}

// softmax rows -> fp16 probs (shuffle reductions; 4 __syncthreads total)
__global__ __launch_bounds__(256)
void softmax_split(const float* __restrict__ S, __half* __restrict__ P16)
{
    const long long row = blockIdx.x;
    const float* p = S + row * (long long)TV;
    __half* o = P16 + row * (long long)TV;
    const int tid  = threadIdx.x;
    const int lane = tid & 31;
    const int wid  = tid >> 5;

    __shared__ float red[8];
    __shared__ float bc;

    float vals[8];
    float lmax = -3.0e38f;
#pragma unroll
    for (int i = 0; i < 2; i++) {
        float4 t = ((const float4*)p)[tid + i * 256];
        vals[i * 4 + 0] = t.x; vals[i * 4 + 1] = t.y;
        vals[i * 4 + 2] = t.z; vals[i * 4 + 3] = t.w;
        lmax = fmaxf(lmax, fmaxf(fmaxf(t.x, t.y), fmaxf(t.z, t.w)));
    }
#pragma unroll
    for (int s = 16; s > 0; s >>= 1)
        lmax = fmaxf(lmax, __shfl_xor_sync(0xffffffffu, lmax, s));
    if (lane == 0) red[wid] = lmax;
    __syncthreads();
    if (wid == 0) {
        float m = (lane < 8) ? red[lane] : -3.0e38f;
#pragma unroll
        for (int s = 4; s > 0; s >>= 1)
            m = fmaxf(m, __shfl_xor_sync(0xffffffffu, m, s));
        if (lane == 0) bc = m;
    }
    __syncthreads();
    const float m = bc;

    float lsum = 0.f;
#pragma unroll
    for (int i = 0; i < 8; i++) { vals[i] = expf(vals[i] - m); lsum += vals[i]; }
#pragma unroll
    for (int s = 16; s > 0; s >>= 1)
        lsum += __shfl_xor_sync(0xffffffffu, lsum, s);
    if (lane == 0) red[wid] = lsum;
    __syncthreads();
    if (wid == 0) {
        float t = (lane < 8) ? red[lane] : 0.f;
#pragma unroll
        for (int s = 4; s > 0; s >>= 1)
            t += __shfl_xor_sync(0xffffffffu, t, s);
        if (lane == 0) bc = 1.f / t;
    }
    __syncthreads();
    const float inv = bc;

#pragma unroll
    for (int i = 0; i < 2; i++) {
        const int e0 = 4 * tid + 1024 * i;
        __half2 a = __floats2half2_rn(vals[i * 4 + 0] * inv, vals[i * 4 + 1] * inv);
        __half2 b = __floats2half2_rn(vals[i * 4 + 2] * inv, vals[i * 4 + 3] * inv);
        ((__half2*)(o + e0))[0] = a;
        ((__half2*)(o + e0))[1] = b;
    }
}

// alignment_t: transpose fp16 probs -> fp32 [b][v][q]
// 64x64 tiles, (16,16) threads, vectorized: half2 loads, float4 stores.
__global__ void transpose_out(const __half* __restrict__ P16, float* __restrict__ out)
{
    __shared__ float t[64][65];
    const int b = blockIdx.z;
    const __half* base = P16 + (long long)b * TQ * TV;
    float* dst = out + (long long)b * TV * TQ;
    const int v0 = blockIdx.x * 64, q0 = blockIdx.y * 64;
    const int tx = threadIdx.x;          // 0..15
    const int ty = threadIdx.y;          // 0..15

#pragma unroll
    for (int i = 0; i < 4; i++) {
        const int qq = q0 + i * 16 + ty;
        const __half2* rp = (const __half2*)(base + (long long)qq * TV + v0);
        const __half2 a  = rp[2 * tx];
        const __half2 b2 = rp[2 * tx + 1];
        t[4 * tx + 0][i * 16 + ty] = __low2float(a);
        t[4 * tx + 1][i * 16 + ty] = __high2float(a);
        t[4 * tx + 2][i * 16 + ty] = __low2float(b2);
        t[4 * tx + 3][i * 16 + ty] = __high2float(b2);
    }
    __syncthreads();
#pragma unroll
    for (int i = 0; i < 4; i++) {
        const int vv = v0 + i * 16 + ty;
        float4 val = make_float4(t[i * 16 + ty][4 * tx + 0],
                                 t[i * 16 + ty][4 * tx + 1],
                                 t[i * 16 + ty][4 * tx + 2],
                                 t[i * 16 + ty][4 * tx + 3]);
        *(float4*)(dst + (long long)vv * TQ + q0 + 4 * tx) = val;
    }
}

// ========================= launch ==========================================
extern "C" void kernel_launch(void* const* d_in, const int* in_sizes, int n_in,
                              void* d_out, int out_size)
{
    (void)in_sizes; (void)n_in; (void)out_size;
    const float* q = (const float*)d_in[0];   // [16,2048,1024]
    const float* v = (const float*)d_in[1];   // [16,2048,512]
    const float* W = (const float*)d_in[2];   // [512,1024]
    // d_in[3] = bias: provably cancels through softmax (per-row constant Q·b).

    float* out       = (float*)d_out;
    float* out_ctx   = out;                                      // [16,2048,1536]
    float* out_align = out + (long long)NB * TQ * 1536;          // [16,2048,2048]

    __nv_bfloat16 *q2, *v2, *w2, *qw2;
    __half *vt16, *p16;
    float* scores;
    cudaGetSymbolAddress((void**)&q2,     g_q2);
    cudaGetSymbolAddress((void**)&v2,     g_v2);
    cudaGetSymbolAddress((void**)&w2,     g_w2);
    cudaGetSymbolAddress((void**)&qw2,    g_qw2);
    cudaGetSymbolAddress((void**)&vt16,   g_vt16);
    cudaGetSymbolAddress((void**)&p16,    g_p16);
    cudaGetSymbolAddress((void**)&scores, g_scores);

    cudaFuncSetAttribute(gemm_mma<0,0>, cudaFuncAttributeMaxDynamicSharedMemorySize, GEMM_DSMEM);
    cudaFuncSetAttribute(gemm_mma<1,0>, cudaFuncAttributeMaxDynamicSharedMemorySize, GEMM_DSMEM);
    cudaFuncSetAttribute(gemm_mma<0,1>, cudaFuncAttributeMaxDynamicSharedMemorySize, GEMM_DSMEM);

    // operand prep (conv_P on query also performs the out_ctx query copy)
    conv_P<<<(NB * TQ * (DEC / 4)) / 256, 256>>>(q, q2, DEC, out_ctx);
    conv_P<<<(ENC * (DEC / 4)) / 256, 256>>>(W, w2, DEC, nullptr);   // W split, K-major in d
    conv_V<<<dim3(ENC / 32, TV / 32, NB), dim3(32, 8)>>>(v, v2, vt16);

    // G1': qw2 = split(Q @ W^T)   [M=TQ, N=ENC, K=1024], bf16 3-pass
    gemm_mma<1,0><<<dim3(ENC / 128, TQ / 128, NB), 256, GEMM_DSMEM>>>(
        q2, w2, nullptr, qw2,
        DEC, (long long)TQ * (2 * DEC) * 2, 0LL,
        (long long)TQ * (2 * ENC), 2 * ENC);

    // G2': scores = QW @ V^T      [M=TQ, N=TV, K=512], bf16 3-pass
    gemm_mma<0,0><<<dim3(TV / 128, TQ / 128, NB), 256, GEMM_DSMEM>>>(
        qw2, v2, scores, nullptr,
        ENC, (long long)TQ * (2 * ENC) * 2, (long long)TV * (2 * ENC) * 2,
        (long long)TQ * TV, TV);

    // softmax -> p16
    softmax_split<<<NB * TQ, 256>>>(scores, p16);

    // G3: context = probs @ value [M=TQ, N=ENC, K=2048], fp16 1-pass
    gemm_mma<0,1><<<dim3(ENC / 128, TQ / 128, NB), 256, GEMM_DSMEM>>>(
        p16, vt16, out_ctx, nullptr,
        TV, (long long)TQ * TV * 2, (long long)ENC * TV * 2,
        (long long)TQ * 1536, 1536);

    // alignment_t = transpose(p16)
    transpose_out<<<dim3(TV / 64, TQ / 64, NB), dim3(16, 16)>>>(p16, out_align);
}